// round 7
// baseline (speedup 1.0000x reference)
#include <cuda_runtime.h>
#include <cuda_bf16.h>
#include <cstdint>

// ---------------------------------------------------------------------------
// Scratch buffer (device global — allocation-rule safe)
// ---------------------------------------------------------------------------
__device__ __align__(1024) __nv_bfloat16 g_xbf[1024ull * 128 * 512]; // (b, c, t) bf16

// ---------------------------------------------------------------------------
// PTX helpers
// ---------------------------------------------------------------------------
__device__ __forceinline__ uint32_t smem_u32(const void* p) {
    uint32_t a;
    asm("{ .reg .u64 t; cvta.to.shared.u64 t, %1; cvt.u32.u64 %0, t; }" : "=r"(a) : "l"(p));
    return a;
}
__device__ __forceinline__ void ldsm_x4(uint32_t* r, uint32_t addr) {
    asm volatile("ldmatrix.sync.aligned.m8n8.x4.shared.b16 {%0,%1,%2,%3}, [%4];"
                 : "=r"(r[0]), "=r"(r[1]), "=r"(r[2]), "=r"(r[3]) : "r"(addr));
}
__device__ __forceinline__ void mma_bf16(float* c, const uint32_t* a, uint32_t b0, uint32_t b1) {
    asm volatile(
        "mma.sync.aligned.m16n8k16.row.col.f32.bf16.bf16.f32 "
        "{%0,%1,%2,%3}, {%4,%5,%6,%7}, {%8,%9}, {%0,%1,%2,%3};"
        : "+f"(c[0]), "+f"(c[1]), "+f"(c[2]), "+f"(c[3])
        : "r"(a[0]), "r"(a[1]), "r"(a[2]), "r"(a[3]), "r"(b0), "r"(b1));
}
#define CP_ASYNC_16(dst, src) \
    asm volatile("cp.async.cg.shared.global [%0], [%1], 16;" :: "r"(dst), "l"(src) : "memory")
#define CP_COMMIT() asm volatile("cp.async.commit_group;" ::: "memory")
#define CP_WAIT(n)  asm volatile("cp.async.wait_group %0;" :: "n"(n) : "memory")

__device__ __forceinline__ uint32_t cluster_rank() {
    uint32_t r;
    asm("mov.u32 %0, %%cluster_ctarank;" : "=r"(r));
    return r;
}
__device__ __forceinline__ uint32_t mapa_u32(uint32_t laddr, uint32_t rank) {
    uint32_t r;
    asm("mapa.shared::cluster.u32 %0, %1, %2;" : "=r"(r) : "r"(laddr), "r"(rank));
    return r;
}
__device__ __forceinline__ void ld_dsmem_8(uint32_t* r, uint32_t addr) {
    asm volatile("ld.shared::cluster.v2.b32 {%0,%1}, [%2];"
                 : "=r"(r[0]), "=r"(r[1]) : "r"(addr));
}
#define CLUSTER_SYNC() do { \
    asm volatile("barrier.cluster.arrive.aligned;" ::: "memory"); \
    asm volatile("barrier.cluster.wait.aligned;" ::: "memory"); \
} while (0)

// ---------------------------------------------------------------------------
// Kernel 1: transpose x (N,C,T,F) fp32 -> g_xbf (b=n*32+f, c, t) bf16
// grid (T/64=8, C=128, N=32), block 256
// ---------------------------------------------------------------------------
__global__ __launch_bounds__(256) void transpose_in_kernel(const float* __restrict__ x) {
    const int t0 = blockIdx.x * 64;
    const int c  = blockIdx.y;
    const int n  = blockIdx.z;
    __shared__ float tile[32][65]; // [f][t-offset]

    const float4* src = (const float4*)(x + (((size_t)(n * 128 + c) * 512 + t0) * 32));
    const int tid = threadIdx.x;

    #pragma unroll
    for (int i = 0; i < 2; i++) {
        int idx = tid + i * 256;     // 0..511 float4s
        int row = idx >> 3;          // t offset 0..63
        int fq  = idx & 7;           // f quad
        float4 v = src[row * 8 + fq];
        tile[fq * 4 + 0][row] = v.x;
        tile[fq * 4 + 1][row] = v.y;
        tile[fq * 4 + 2][row] = v.z;
        tile[fq * 4 + 3][row] = v.w;
    }
    __syncthreads();

    const int f  = tid >> 3;         // 0..31
    const int t8 = (tid & 7) * 8;    // 0..56
    __nv_bfloat162 o[4];
    #pragma unroll
    for (int q = 0; q < 4; q++)
        o[q] = __floats2bfloat162_rn(tile[f][t8 + 2 * q], tile[f][t8 + 2 * q + 1]);
    *(float4*)(&g_xbf[(((size_t)(n * 32 + f) * 128 + c) << 9) + t0 + t8]) = *(float4*)o;
}

// ---------------------------------------------------------------------------
// Kernel 2: per-batch bf16 HMMA SYRK + gaussian epilogue + cluster-8 DSMEM
// f-exchange writing the final (n, i, j, f) fp32 output directly.
// 1024 CTAs (cluster of 8 = f0..f0+7, same n), 256 threads = 8 warps.
// ---------------------------------------------------------------------------
#define GK_BK     64
#define GK_PAD    72
#define GK_TILE   (128 * GK_PAD)          // bf16 elements per stage
#define GK_STAGES 4
#define GK_DSMEM  (GK_STAGES * GK_TILE * 2)  // 73728 B
#define XC_PAD    136                     // exchange row stride (bf16), 272 B
#define XC_BYTES  (128 * XC_PAD * 2)      // 34816 B  (< GK_DSMEM, reuses ring)

extern "C" __global__ __launch_bounds__(256, 2) __cluster_dims__(8, 1, 1)
void gram_mma_kernel(const float* __restrict__ sigma, float* __restrict__ out) {
    extern __shared__ __align__(128) __nv_bfloat16 As[]; // ring; reused for exchange
    __shared__ float diag_s[128];

    const int tid  = threadIdx.x;
    const int lane = tid & 31;
    const int wid  = tid >> 5;
    const int b    = blockIdx.x;
    const int n    = b >> 5;
    const int f0   = (b & 31) & ~7;
    const uint32_t rank = cluster_rank();   // == b & 7

    const int wm = (wid & 3) * 32;   // warp M offset
    const int wn = (wid >> 2) * 64;  // warp N offset

    const __nv_bfloat16* A = g_xbf + (size_t)b * 128 * 512;

    // cp.async mapping: thread -> row (tid>>1), 4 chunks of 16B
    const int ld_row = tid >> 1;
    const int ld_ch0 = (tid & 1) * 4;
    const __nv_bfloat16* gsrc = A + (size_t)ld_row * 512 + ld_ch0 * 8;
    const uint32_t s_base = smem_u32(As);
    const uint32_t s_row = s_base + (uint32_t)(ld_row * GK_PAD + ld_ch0 * 8) * 2;

    // ldmatrix per-lane offsets (bytes), row stride = GK_PAD*2 = 144B
    const int a_row = wm + ((lane >> 3) & 1) * 8 + (lane & 7);
    const int a_kx  = (lane >> 4) * 8;
    const int b_row = wn + (lane >> 4) * 8 + (lane & 7);
    const int b_kx  = ((lane >> 3) & 1) * 8;
    const uint32_t a_off = (uint32_t)(a_row * GK_PAD + a_kx) * 2;
    const uint32_t b_off = (uint32_t)(b_row * GK_PAD + b_kx) * 2;

    float acc[2][8][4];
    #pragma unroll
    for (int mi = 0; mi < 2; mi++)
        #pragma unroll
        for (int ni = 0; ni < 8; ni++)
            #pragma unroll
            for (int e = 0; e < 4; e++) acc[mi][ni][e] = 0.0f;

    // prologue: chunks 0..2 -> stages 0..2
    #pragma unroll
    for (int s = 0; s < GK_STAGES - 1; s++) {
        const uint32_t dsts = s_row + s * (GK_TILE * 2);
        const __nv_bfloat16* srcs = gsrc + s * GK_BK;
        #pragma unroll
        for (int c4 = 0; c4 < 4; c4++)
            CP_ASYNC_16(dsts + c4 * 16, srcs + c4 * 8);
        CP_COMMIT();
    }

    #pragma unroll 1
    for (int kt = 0; kt < 8; kt++) {
        CP_WAIT(GK_STAGES - 2);
        __syncthreads();

        const uint32_t buf = s_base + (kt & (GK_STAGES - 1)) * (GK_TILE * 2);
        const uint32_t ab = buf + a_off;
        const uint32_t bb = buf + b_off;

        #pragma unroll
        for (int ks = 0; ks < 4; ks++) {
            const uint32_t ko = ks * 32;
            uint32_t ar[2][4];
            ldsm_x4(ar[0], ab + ko);
            ldsm_x4(ar[1], ab + 16 * GK_PAD * 2 + ko);
            uint32_t br[4][4];
            #pragma unroll
            for (int nt = 0; nt < 4; nt++)
                ldsm_x4(br[nt], bb + nt * 16 * GK_PAD * 2 + ko);
            #pragma unroll
            for (int mi = 0; mi < 2; mi++)
                #pragma unroll
                for (int ni = 0; ni < 8; ni++)
                    mma_bf16(acc[mi][ni], ar[mi],
                             br[ni >> 1][(ni & 1) * 2], br[ni >> 1][(ni & 1) * 2 + 1]);
        }

        if (kt + GK_STAGES - 1 < 8) {
            const uint32_t dsts = s_row + ((kt + GK_STAGES - 1) & (GK_STAGES - 1)) * (GK_TILE * 2);
            const __nv_bfloat16* srcs = gsrc + (kt + GK_STAGES - 1) * GK_BK;
            #pragma unroll
            for (int c4 = 0; c4 < 4; c4++)
                CP_ASYNC_16(dsts + c4 * 16, srcs + c4 * 8);
        }
        CP_COMMIT();
    }

    // ---- diag extraction (exact: from same accumulators) ----
    const int tr = lane >> 2;          // 0..7
    const int tc = (lane & 3) * 2;     // 0,2,4,6
    #pragma unroll
    for (int mi = 0; mi < 2; mi++)
        #pragma unroll
        for (int ni = 0; ni < 8; ni++) {
            const int gm0 = wm + mi * 16 + tr;
            const int gm1 = gm0 + 8;
            const int gn  = wn + ni * 8 + tc;
            if (gm0 == gn)     diag_s[gm0] = acc[mi][ni][0];
            if (gm0 == gn + 1) diag_s[gm0] = acc[mi][ni][1];
            if (gm1 == gn)     diag_s[gm1] = acc[mi][ni][2];
            if (gm1 == gn + 1) diag_s[gm1] = acc[mi][ni][3];
        }
    __syncthreads();   // also: all warps done with ring smem -> safe to reuse

    const float sg  = sigma[0];
    const float inv = 1.0f / (2.0f * sg * sg);
    __nv_bfloat16* vals = As;          // [128][XC_PAD] bf16, row stride 272B

    #pragma unroll
    for (int mi = 0; mi < 2; mi++) {
        const int gm0 = wm + mi * 16 + tr;
        const int gm1 = gm0 + 8;
        const float d0 = diag_s[gm0];
        const float d1 = diag_s[gm1];
        #pragma unroll
        for (int ni = 0; ni < 8; ni++) {
            const int gn = wn + ni * 8 + tc;
            const float e0 = diag_s[gn];
            const float e1 = diag_s[gn + 1];
            float a00 = fmaxf(d0 + e0 - 2.0f * acc[mi][ni][0], 0.0f) * inv;
            float a01 = fmaxf(d0 + e1 - 2.0f * acc[mi][ni][1], 0.0f) * inv;
            float a10 = fmaxf(d1 + e0 - 2.0f * acc[mi][ni][2], 0.0f) * inv;
            float a11 = fmaxf(d1 + e1 - 2.0f * acc[mi][ni][3], 0.0f) * inv;
            float r00 = 0.0f, r01 = 0.0f, r10 = 0.0f, r11 = 0.0f;
            // warp-vote skip: MUFU only issued when some lane is near-diagonal
            const float amin = fminf(fminf(a00, a01), fminf(a10, a11));
            if (__any_sync(0xffffffffu, amin < 87.0f)) {
                r00 = (a00 < 87.0f) ? __expf(-a00) : 0.0f;
                r01 = (a01 < 87.0f) ? __expf(-a01) : 0.0f;
                r10 = (a10 < 87.0f) ? __expf(-a10) : 0.0f;
                r11 = (a11 < 87.0f) ? __expf(-a11) : 0.0f;
            }
            *(__nv_bfloat162*)(vals + gm0 * XC_PAD + gn) = __floats2bfloat162_rn(r00, r01);
            *(__nv_bfloat162*)(vals + gm1 * XC_PAD + gn) = __floats2bfloat162_rn(r10, r11);
        }
    }

    CLUSTER_SYNC();   // all 8 CTAs' vals visible cluster-wide

    // ---- DSMEM gather + final store ----
    // This CTA owns j-slice [rank*16, rank*16+16). Thread t: i = t>>1,
    // j0 = rank*16 + (t&1)*8. For each peer p (f = f0+p): read vals_p[i][j0..j0+7]
    // (16B), then per j write out[n][i][j][f0..f0+7] = 32B (2 float4, evict-first).
    {
        const int i  = tid >> 1;
        const int j0 = (int)rank * 16 + (tid & 1) * 8;
        const uint32_t laddr = s_base + (uint32_t)(i * XC_PAD + j0) * 2;

        uint32_t rf[8][4];
        #pragma unroll
        for (int p = 0; p < 8; p++) {
            const uint32_t raddr = mapa_u32(laddr, (uint32_t)p);
            ld_dsmem_8(&rf[p][0], raddr);
            ld_dsmem_8(&rf[p][2], raddr + 8);
        }

        float* outp = out + (((size_t)(n * 128 + i) * 128) + j0) * 32 + f0;
        #pragma unroll
        for (int jj = 0; jj < 8; jj++) {
            float fo[8];
            #pragma unroll
            for (int p = 0; p < 8; p++) {
                const __nv_bfloat162 h2 =
                    *(__nv_bfloat162*)&rf[p][jj >> 1];
                fo[p] = (jj & 1) ? __high2float(h2) : __low2float(h2);
            }
            float4* dst = (float4*)(outp + (size_t)jj * 32);
            __stcs(dst,     make_float4(fo[0], fo[1], fo[2], fo[3]));
            __stcs(dst + 1, make_float4(fo[4], fo[5], fo[6], fo[7]));
        }
    }

    CLUSTER_SYNC();   // keep smem alive until all peers finished reading
}

// ---------------------------------------------------------------------------
extern "C" void kernel_launch(void* const* d_in, const int* in_sizes, int n_in,
                              void* d_out, int out_size) {
    const float* x;
    const float* sigma;
    if (in_sizes[0] == 1) {
        sigma = (const float*)d_in[0];
        x     = (const float*)d_in[1];
    } else {
        x     = (const float*)d_in[0];
        sigma = (const float*)d_in[1];
    }
    float* out = (float*)d_out;

    static bool attr_set = false;
    if (!attr_set) {
        cudaFuncSetAttribute(gram_mma_kernel,
                             cudaFuncAttributeMaxDynamicSharedMemorySize, GK_DSMEM);
        attr_set = true;
    }

    transpose_in_kernel<<<dim3(8, 128, 32), 256>>>(x);
    gram_mma_kernel<<<1024, 256, GK_DSMEM>>>(sigma, out);
}

// round 13
// speedup vs baseline: 1.7610x; 1.7610x over previous
#include <cuda_runtime.h>
#include <cuda_bf16.h>
#include <cstdint>

// ---------------------------------------------------------------------------
// Scratch buffers (device globals — allocation-rule safe)
// ---------------------------------------------------------------------------
__device__ __align__(1024) __nv_bfloat16 g_xbf[1024ull * 128 * 512]; // (b, c, t) bf16
__device__ __align__(1024) __nv_bfloat16 g_kbf[1024ull * 128 * 128]; // (b, i, j) bf16

// ---------------------------------------------------------------------------
// PTX helpers
// ---------------------------------------------------------------------------
__device__ __forceinline__ uint32_t smem_u32(const void* p) {
    uint32_t a;
    asm("{ .reg .u64 t; cvta.to.shared.u64 t, %1; cvt.u32.u64 %0, t; }" : "=r"(a) : "l"(p));
    return a;
}
__device__ __forceinline__ void ldsm_x4(uint32_t* r, uint32_t addr) {
    asm volatile("ldmatrix.sync.aligned.m8n8.x4.shared.b16 {%0,%1,%2,%3}, [%4];"
                 : "=r"(r[0]), "=r"(r[1]), "=r"(r[2]), "=r"(r[3]) : "r"(addr));
}
__device__ __forceinline__ void mma_bf16(float* c, const uint32_t* a, uint32_t b0, uint32_t b1) {
    asm volatile(
        "mma.sync.aligned.m16n8k16.row.col.f32.bf16.bf16.f32 "
        "{%0,%1,%2,%3}, {%4,%5,%6,%7}, {%8,%9}, {%0,%1,%2,%3};"
        : "+f"(c[0]), "+f"(c[1]), "+f"(c[2]), "+f"(c[3])
        : "r"(a[0]), "r"(a[1]), "r"(a[2]), "r"(a[3]), "r"(b0), "r"(b1));
}
#define CP_ASYNC_16(dst, src) \
    asm volatile("cp.async.cg.shared.global [%0], [%1], 16;" :: "r"(dst), "l"(src) : "memory")
#define CP_COMMIT() asm volatile("cp.async.commit_group;" ::: "memory")
#define CP_WAIT(n)  asm volatile("cp.async.wait_group %0;" :: "n"(n) : "memory")

// ---------------------------------------------------------------------------
// Kernel 1: transpose x (N,C,T,F) fp32 -> g_xbf (b=n*32+f, c, t) bf16
// grid (T/64=8, C=128, N=32), block 256
// ---------------------------------------------------------------------------
__global__ __launch_bounds__(256) void transpose_in_kernel(const float* __restrict__ x) {
    const int t0 = blockIdx.x * 64;
    const int c  = blockIdx.y;
    const int n  = blockIdx.z;
    __shared__ float tile[32][65]; // [f][t-offset]

    const float4* src = (const float4*)(x + (((size_t)(n * 128 + c) * 512 + t0) * 32));
    const int tid = threadIdx.x;

    #pragma unroll
    for (int i = 0; i < 2; i++) {
        int idx = tid + i * 256;     // 0..511 float4s
        int row = idx >> 3;          // t offset 0..63
        int fq  = idx & 7;           // f quad
        float4 v = src[row * 8 + fq];
        tile[fq * 4 + 0][row] = v.x;
        tile[fq * 4 + 1][row] = v.y;
        tile[fq * 4 + 2][row] = v.z;
        tile[fq * 4 + 3][row] = v.w;
    }
    __syncthreads();

    const int f  = tid >> 3;         // 0..31
    const int t8 = (tid & 7) * 8;    // 0..56
    __nv_bfloat162 o[4];
    #pragma unroll
    for (int q = 0; q < 4; q++)
        o[q] = __floats2bfloat162_rn(tile[f][t8 + 2 * q], tile[f][t8 + 2 * q + 1]);
    *(float4*)(&g_xbf[(((size_t)(n * 32 + f) * 128 + c) << 9) + t0 + t8]) = *(float4*)o;
}

// ---------------------------------------------------------------------------
// Kernel 2: per-batch bf16 HMMA SYRK exploiting symmetry (G = X X^T).
// 10 unique 32x32 blocks of the 128x128 output -> 5 warps x 2 blocks each.
// 160 threads/CTA, 4-stage cp.async ring. Epilogue: exp values (and their
// mirrors) scattered into a 128x136 smem tile (reuses ring), then one
// coalesced copy to g_kbf (bf16 — exact here: output values are {0,1}).
// ---------------------------------------------------------------------------
#define GK_BK     64
#define GK_PAD    72
#define GK_TILE   (128 * GK_PAD)             // bf16 elements per stage
#define GK_STAGES 4
#define GK_DSMEM  (GK_STAGES * GK_TILE * 2)  // 73728 B
#define XC_PAD    136                        // epilogue tile row stride (bf16)

extern "C" __global__ __launch_bounds__(160, 3)
void gram_mma_kernel(const float* __restrict__ sigma) {
    extern __shared__ __align__(128) __nv_bfloat16 As[]; // ring; reused as epi tile
    __shared__ float diag_s[128];

    const int tid  = threadIdx.x;
    const int lane = tid & 31;
    const int wid  = tid >> 5;          // 0..4
    const int b    = blockIdx.x;

    // warp -> 2 blocks (p = m-group, q = n-group), all 10 unique, balanced
    const int tabP[5][2] = {{0,1},{1,0},{2,0},{3,1},{0,2}};
    const int tabQ[5][2] = {{0,2},{1,3},{2,1},{3,3},{2,3}};
    const int P0 = tabP[wid][0], Q0 = tabQ[wid][0];
    const int P1 = tabP[wid][1], Q1 = tabQ[wid][1];

    const __nv_bfloat16* A = g_xbf + (size_t)b * 128 * 512;

    // cp.async mapping: threads 0..127, one full row (8 x 16B) each
    const __nv_bfloat16* gsrc = A + (size_t)tid * 512;
    const uint32_t s_base = smem_u32(As);
    const uint32_t s_row  = s_base + (uint32_t)(tid * GK_PAD) * 2;
    const bool loader = (tid < 128);

    // ldmatrix lane-local offsets (bytes), row stride = GK_PAD*2 = 144B
    const int arl  = ((lane >> 3) & 1) * 8 + (lane & 7);
    const int akx  = (lane >> 4) * 8;
    const int brl  = (lane >> 4) * 8 + (lane & 7);
    const int bkx  = ((lane >> 3) & 1) * 8;
    const uint32_t a_off0 = (uint32_t)((32 * P0 + arl) * GK_PAD + akx) * 2;
    const uint32_t a_off1 = (uint32_t)((32 * P1 + arl) * GK_PAD + akx) * 2;
    const uint32_t b_off0 = (uint32_t)((32 * Q0 + brl) * GK_PAD + bkx) * 2;
    const uint32_t b_off1 = (uint32_t)((32 * Q1 + brl) * GK_PAD + bkx) * 2;

    float acc[2][2][4][4];  // [blk][mi][ni][e]
    #pragma unroll
    for (int blk = 0; blk < 2; blk++)
        #pragma unroll
        for (int mi = 0; mi < 2; mi++)
            #pragma unroll
            for (int ni = 0; ni < 4; ni++)
                #pragma unroll
                for (int e = 0; e < 4; e++) acc[blk][mi][ni][e] = 0.0f;

    // prologue: chunks 0..2 -> stages 0..2
    #pragma unroll
    for (int s = 0; s < GK_STAGES - 1; s++) {
        if (loader) {
            const uint32_t dsts = s_row + s * (GK_TILE * 2);
            const __nv_bfloat16* srcs = gsrc + s * GK_BK;
            #pragma unroll
            for (int c8 = 0; c8 < 8; c8++)
                CP_ASYNC_16(dsts + c8 * 16, srcs + c8 * 8);
        }
        CP_COMMIT();
    }

    #pragma unroll 1
    for (int kt = 0; kt < 8; kt++) {
        CP_WAIT(GK_STAGES - 2);
        __syncthreads();

        const uint32_t buf = s_base + (kt & (GK_STAGES - 1)) * (GK_TILE * 2);
        const uint32_t ab0 = buf + a_off0, ab1 = buf + a_off1;
        const uint32_t bb0 = buf + b_off0, bb1 = buf + b_off1;

        #pragma unroll
        for (int ks = 0; ks < 4; ks++) {
            const uint32_t ko = ks * 32;           // 16 bf16 = 32B per k-step
            uint32_t ar[2][2][4], br[2][2][4];
            ldsm_x4(ar[0][0], ab0 + ko);
            ldsm_x4(ar[0][1], ab0 + 16 * GK_PAD * 2 + ko);
            ldsm_x4(br[0][0], bb0 + ko);
            ldsm_x4(br[0][1], bb0 + 16 * GK_PAD * 2 + ko);
            ldsm_x4(ar[1][0], ab1 + ko);
            ldsm_x4(ar[1][1], ab1 + 16 * GK_PAD * 2 + ko);
            ldsm_x4(br[1][0], bb1 + ko);
            ldsm_x4(br[1][1], bb1 + 16 * GK_PAD * 2 + ko);
            #pragma unroll
            for (int blk = 0; blk < 2; blk++)
                #pragma unroll
                for (int mi = 0; mi < 2; mi++)
                    #pragma unroll
                    for (int ni = 0; ni < 4; ni++)
                        mma_bf16(acc[blk][mi][ni], ar[blk][mi],
                                 br[blk][ni >> 1][(ni & 1) * 2],
                                 br[blk][ni >> 1][(ni & 1) * 2 + 1]);
        }

        if (kt + GK_STAGES - 1 < 8 && loader) {
            const uint32_t dsts = s_row + ((kt + GK_STAGES - 1) & (GK_STAGES - 1)) * (GK_TILE * 2);
            const __nv_bfloat16* srcs = gsrc + (kt + GK_STAGES - 1) * GK_BK;
            #pragma unroll
            for (int c8 = 0; c8 < 8; c8++)
                CP_ASYNC_16(dsts + c8 * 16, srcs + c8 * 8);
        }
        CP_COMMIT();
    }

    // ---- phase 1: diag extraction (exact: from same accumulators) ----
    const int tr = lane >> 2;          // 0..7
    const int tc = (lane & 3) * 2;     // 0,2,4,6
    #pragma unroll
    for (int blk = 0; blk < 2; blk++) {
        const int p = (blk == 0) ? P0 : P1;
        const int q = (blk == 0) ? Q0 : Q1;
        if (p == q) {
            #pragma unroll
            for (int mi = 0; mi < 2; mi++)
                #pragma unroll
                for (int ni = 0; ni < 4; ni++) {
                    const int gm0 = 32 * p + mi * 16 + tr;
                    const int gm1 = gm0 + 8;
                    const int gn  = 32 * q + ni * 8 + tc;
                    if (gm0 == gn)     diag_s[gm0] = acc[blk][mi][ni][0];
                    if (gm0 == gn + 1) diag_s[gm0] = acc[blk][mi][ni][1];
                    if (gm1 == gn)     diag_s[gm1] = acc[blk][mi][ni][2];
                    if (gm1 == gn + 1) diag_s[gm1] = acc[blk][mi][ni][3];
                }
        }
    }
    __syncthreads();   // diag ready; ring smem free for reuse

    // ---- phase 2: exp + scatter (with mirrors) into smem tile ----
    const float sg  = sigma[0];
    const float inv = 1.0f / (2.0f * sg * sg);
    __nv_bfloat16* vals = As;          // [128][XC_PAD]

    #pragma unroll
    for (int blk = 0; blk < 2; blk++) {
        const int p = (blk == 0) ? P0 : P1;
        const int q = (blk == 0) ? Q0 : Q1;
        #pragma unroll
        for (int mi = 0; mi < 2; mi++) {
            const int gm0 = 32 * p + mi * 16 + tr;
            const int gm1 = gm0 + 8;
            const float d0 = diag_s[gm0];
            const float d1 = diag_s[gm1];
            #pragma unroll
            for (int ni = 0; ni < 4; ni++) {
                const int gn = 32 * q + ni * 8 + tc;
                const float e0 = diag_s[gn];
                const float e1 = diag_s[gn + 1];
                float a00 = fmaxf(d0 + e0 - 2.0f * acc[blk][mi][ni][0], 0.0f) * inv;
                float a01 = fmaxf(d0 + e1 - 2.0f * acc[blk][mi][ni][1], 0.0f) * inv;
                float a10 = fmaxf(d1 + e0 - 2.0f * acc[blk][mi][ni][2], 0.0f) * inv;
                float a11 = fmaxf(d1 + e1 - 2.0f * acc[blk][mi][ni][3], 0.0f) * inv;
                float r00 = 0.0f, r01 = 0.0f, r10 = 0.0f, r11 = 0.0f;
                // warp-vote skip: MUFU only issued when some lane is near-diag
                const float amin = fminf(fminf(a00, a01), fminf(a10, a11));
                if (__any_sync(0xffffffffu, amin < 87.0f)) {
                    r00 = (a00 < 87.0f) ? __expf(-a00) : 0.0f;
                    r01 = (a01 < 87.0f) ? __expf(-a01) : 0.0f;
                    r10 = (a10 < 87.0f) ? __expf(-a10) : 0.0f;
                    r11 = (a11 < 87.0f) ? __expf(-a11) : 0.0f;
                }
                *(__nv_bfloat162*)(vals + gm0 * XC_PAD + gn) = __floats2bfloat162_rn(r00, r01);
                *(__nv_bfloat162*)(vals + gm1 * XC_PAD + gn) = __floats2bfloat162_rn(r10, r11);
                if (p != q) {
                    vals[gn * XC_PAD + gm0]       = __float2bfloat16(r00);
                    vals[gn * XC_PAD + gm1]       = __float2bfloat16(r10);
                    vals[(gn + 1) * XC_PAD + gm0] = __float2bfloat16(r01);
                    vals[(gn + 1) * XC_PAD + gm1] = __float2bfloat16(r11);
                }
            }
        }
    }
    __syncthreads();

    // ---- phase 3: coalesced copy smem tile -> g_kbf ----
    // 16384 bf16 = 2048 float4 (8 bf16 each); 16 float4 per 128-bf16 row.
    __nv_bfloat16* outb = g_kbf + (size_t)b * 16384;
    #pragma unroll 1
    for (int u = tid; u < 2048; u += 160) {
        const int row = u >> 4;
        const int c8  = (u & 15) * 8;
        float4 v = *(float4*)(vals + row * XC_PAD + c8);
        *(float4*)(outb + row * 128 + c8) = v;
    }
}

// ---------------------------------------------------------------------------
// Kernel 3: transpose g_kbf (n*32+f, i, j) bf16 -> out (n, i, j, f) fp32
// grid (i=128, n=32), block 128. smem-staged, conflict-free, float4 writes.
// ---------------------------------------------------------------------------
__global__ __launch_bounds__(128) void transpose_out_kernel(float* __restrict__ out) {
    const int i = blockIdx.x;
    const int n = blockIdx.y;
    __shared__ float tile[32][129]; // [f][j]

    const int tid = threadIdx.x;

    // Load: each thread: f = tid>>2, j0 = (tid&3)*32 -> 32 bf16 = 4 x 16B loads
    {
        const int f  = tid >> 2;
        const int j0 = (tid & 3) * 32;
        const __nv_bfloat16* src =
            g_kbf + (size_t)(n * 32 + f) * 16384 + (size_t)i * 128 + j0;
        #pragma unroll
        for (int q = 0; q < 4; q++) {
            float4 raw = __ldcs((const float4*)(src + q * 8));
            const __nv_bfloat162* p2 = (const __nv_bfloat162*)&raw;
            #pragma unroll
            for (int h = 0; h < 4; h++) {
                float2 f2 = __bfloat1622float2(p2[h]);
                tile[f][j0 + q * 8 + h * 2]     = f2.x;
                tile[f][j0 + q * 8 + h * 2 + 1] = f2.y;
            }
        }
    }
    __syncthreads();

    // Write: thread t -> column j = t (0..127): out[n][i][j][0..31], 128B contiguous
    const int j = tid;
    float v[32];
    #pragma unroll
    for (int f = 0; f < 32; f++) v[f] = tile[f][j];  // bank = (f + j) % 32: conflict-free
    float4* dst = (float4*)(out + (((size_t)(n * 128 + i) * 128) + j) * 32);
    #pragma unroll
    for (int q = 0; q < 8; q++)
        __stcs(dst + q, make_float4(v[q * 4], v[q * 4 + 1], v[q * 4 + 2], v[q * 4 + 3]));
}

// ---------------------------------------------------------------------------
extern "C" void kernel_launch(void* const* d_in, const int* in_sizes, int n_in,
                              void* d_out, int out_size) {
    const float* x;
    const float* sigma;
    if (in_sizes[0] == 1) {
        sigma = (const float*)d_in[0];
        x     = (const float*)d_in[1];
    } else {
        x     = (const float*)d_in[0];
        sigma = (const float*)d_in[1];
    }
    float* out = (float*)d_out;

    static bool attr_set = false;
    if (!attr_set) {
        cudaFuncSetAttribute(gram_mma_kernel,
                             cudaFuncAttributeMaxDynamicSharedMemorySize, GK_DSMEM);
        attr_set = true;
    }

    transpose_in_kernel<<<dim3(8, 128, 32), 256>>>(x);
    gram_mma_kernel<<<1024, 160, GK_DSMEM>>>(sigma);
    transpose_out_kernel<<<dim3(128, 32), 128>>>(out);
}